// round 1
// baseline (speedup 1.0000x reference)
#include <cuda_runtime.h>
#include <cuda_bf16.h>
#include <cstdint>

#define B_ 1024
#define T_ 200
#define D_ 128
#define U_ 128
#define G_ 384   // 3*U

// Scratch: xm = X@W + b_in, layout [B][T][3U]. Static __device__ (no cudaMalloc allowed).
__device__ float g_xm[(size_t)B_ * T_ * G_];
__device__ int   g_perm[B_];

// ---------- f32x2 helpers (Blackwell packed fp32 FMA: 2 FMAs / instr) ----------
__device__ __forceinline__ unsigned long long pack_dup(float x) {
    unsigned long long r;
    asm("mov.b64 %0, {%1, %1};" : "=l"(r) : "f"(x));
    return r;
}
__device__ __forceinline__ void ffma2(unsigned long long& d, unsigned long long a, unsigned long long b) {
    asm("fma.rn.f32x2 %0, %1, %2, %0;" : "+l"(d) : "l"(a), "l"(b));
}
__device__ __forceinline__ float2 unpack2(unsigned long long v) {
    float2 f;
    asm("mov.b64 {%0, %1}, %2;" : "=f"(f.x), "=f"(f.y) : "l"(v));
    return f;
}

__device__ __forceinline__ float sigm(float x) {
    return __fdividef(1.0f, 1.0f + __expf(-x));
}
__device__ __forceinline__ float tanh_fast(float x) {
    // robust at +-inf: x->-inf: 1-2 = -1 ; x->+inf: 1-0 = 1
    return 1.0f - __fdividef(2.0f, __expf(2.0f * x) + 1.0f);
}

// ---------- Kernel 0: sort batch rows by sequence length (bitonic, 1 block) ----------
__global__ void sort_rows_kernel(const int* __restrict__ slen) {
    __shared__ int key[B_];
    int tid = threadIdx.x;
    // key packs (len, idx): len<=199 so len*1024+idx < 2^18, stable & deterministic
    key[tid] = slen[tid] * 1024 + tid;
    __syncthreads();
    for (int size = 2; size <= B_; size <<= 1) {
        for (int stride = size >> 1; stride > 0; stride >>= 1) {
            int j = tid ^ stride;
            if (j > tid) {
                int a = key[tid], b = key[j];
                bool up = (tid & size) == 0;
                if ((a > b) == up) { key[tid] = b; key[j] = a; }
            }
            __syncthreads();
        }
    }
    g_perm[tid] = key[tid] & (B_ - 1);
}

// ---------- Kernel 1: input GEMM xm[b][t][g] = sum_k X[b][t][k] * W[k][g] + b_in[g] ----------
// grid = (3 n-tiles of 128, 4 t-tiles of 64, B). Early-exits tiles past seq length.
__global__ __launch_bounds__(256) void gemm_in_kernel(
    const float* __restrict__ X, const int* __restrict__ slen,
    const float* __restrict__ W, const float* __restrict__ bias)
{
    int b  = blockIdx.z;
    int t0 = blockIdx.y * 64;
    int n0 = blockIdx.x * 128;
    int len = slen[b];
    if (t0 >= len) return;   // xm beyond len is never used un-masked

    extern __shared__ float sm[];
    float* Xs = sm;              // [64][128]
    float* Ws = sm + 64 * 128;   // [128][128]
    int tid = threadIdx.x;

    // load X tile (coalesced float4), zero rows past T
    const float4* Xg = (const float4*)(X + (size_t)b * T_ * D_);
    float4* Xs4 = (float4*)Xs;
#pragma unroll
    for (int i = 0; i < 8; i++) {
        int idx = i * 256 + tid;          // float4 index: row = idx/32, kq = idx%32
        int row = idx >> 5;
        int t = t0 + row;
        float4 v = make_float4(0.f, 0.f, 0.f, 0.f);
        if (t < T_) v = Xg[t * 32 + (idx & 31)];
        Xs4[idx] = v;
    }
    // load W tile [128 k][128 cols]
    float4* Ws4 = (float4*)Ws;
#pragma unroll
    for (int i = 0; i < 16; i++) {
        int idx = i * 256 + tid;          // k = idx/32, cq = idx%32
        int k = idx >> 5, cq = idx & 31;
        Ws4[idx] = *(const float4*)(W + (size_t)k * G_ + n0 + cq * 4);
    }
    __syncthreads();

    // thread tile: 4 rows x 8 cols, f32x2 pairs over columns (W pairs load as aligned LDS)
    int rg = tid >> 4;        // 0..15 -> rows rg*4..rg*4+3
    int c0 = (tid & 15) * 8;  // 8 cols
    unsigned long long acc[4][4];
#pragma unroll
    for (int p = 0; p < 4; p++)
#pragma unroll
        for (int c = 0; c < 4; c++) acc[p][c] = 0ULL;

#pragma unroll 8
    for (int k = 0; k < 128; k++) {
        ulonglong2 wa = *(const ulonglong2*)(Ws + k * 128 + c0);
        ulonglong2 wb = *(const ulonglong2*)(Ws + k * 128 + c0 + 4);
#pragma unroll
        for (int p = 0; p < 4; p++) {
            unsigned long long xv = pack_dup(Xs[(rg * 4 + p) * 128 + k]);
            ffma2(acc[p][0], xv, wa.x);
            ffma2(acc[p][1], xv, wa.y);
            ffma2(acc[p][2], xv, wb.x);
            ffma2(acc[p][3], xv, wb.y);
        }
    }

    float bi[8];
#pragma unroll
    for (int c = 0; c < 8; c++) bi[c] = bias[n0 + c0 + c];

#pragma unroll
    for (int p = 0; p < 4; p++) {
        int t = t0 + rg * 4 + p;
        if (t >= T_) continue;
        float* op = g_xm + ((size_t)b * T_ + t) * G_ + n0 + c0;
        float2 f0 = unpack2(acc[p][0]);
        float2 f1 = unpack2(acc[p][1]);
        float2 f2 = unpack2(acc[p][2]);
        float2 f3 = unpack2(acc[p][3]);
        float4 o0 = make_float4(f0.x + bi[0], f0.y + bi[1], f1.x + bi[2], f1.y + bi[3]);
        float4 o1 = make_float4(f2.x + bi[4], f2.y + bi[5], f3.x + bi[6], f3.y + bi[7]);
        *(float4*)op = o0;
        *(float4*)(op + 4) = o1;
    }
}

// ---------- Kernel 2: recurrence. 128 blocks x 8 (length-sorted) batch rows, 384 threads ----------
// smem: R (192KB, loaded once) + hT[128][10] (padded) + inner[8][384]
__global__ __launch_bounds__(384, 1) void recur_kernel(
    const int* __restrict__ slen, const float* __restrict__ R,
    const float* __restrict__ bias, float* __restrict__ out)
{
    extern __shared__ float sm[];
    float* R_s = sm;                       // [128][384]
    float* hT  = sm + 128 * 384;           // [128][10] (8 rows + 2 pad)
    float* inn = hT + 128 * 10;            // [8][384]
    __shared__ int rows_s[8], len_s[8];

    int tid = threadIdx.x;   // == gate column g (0..383)

    // load R into smem, coalesced
    {
        float4* Rs4 = (float4*)R_s;
        const float4* Rg4 = (const float4*)R;
#pragma unroll
        for (int i = 0; i < 32; i++) Rs4[i * 384 + tid] = Rg4[i * 384 + tid];
    }
    if (tid < 8) {
        int row = g_perm[blockIdx.x * 8 + tid];
        rows_s[tid] = row;
        len_s[tid] = slen[row];
    }
    for (int i = tid; i < 128 * 10; i += 384) hT[i] = 0.0f;
    unsigned long long br2 = pack_dup(bias[G_ + tid]);
    __syncthreads();

    int maxlen = 0;
#pragma unroll
    for (int r = 0; r < 8; r++) maxlen = max(maxlen, len_s[r]);

    // per-thread combine items: i = tid + 384*s covers 1024 = 8 rows x 128 units
    int uu[3], rr_[3], lenr[3];
    size_t obase[3], xbase[3];
#pragma unroll
    for (int s = 0; s < 3; s++) {
        int i = tid + s * 384;
        int u = i & 127, r = (i >> 7) & 7;
        uu[s] = u; rr_[s] = r;
        if (i < 1024) {
            lenr[s] = len_s[r];
            obase[s] = (size_t)rows_s[r] * T_ * U_ + u;
            xbase[s] = (size_t)rows_s[r] * T_ * G_ + u;
        } else {
            lenr[s] = 0; obase[s] = 0; xbase[s] = 0;
        }
    }
    float po0 = 0.f, po1 = 0.f, po2 = 0.f;

    const float* rp = R_s + tid;

    for (int t = 0; t < maxlen; t++) {
        // prefetch xm for this step (hidden behind the matmul)
        float xz[3], xr[3], xh[3];
#pragma unroll
        for (int s = 0; s < 3; s++) {
            if (s < 2 || tid < 256) {
                const float* xp = g_xm + xbase[s] + (size_t)t * G_;
                xz[s] = xp[0];
                xr[s] = xp[128];
                xh[s] = xp[256];
            }
        }

        // phase 1: inner[r][g] = b_rec[g] + sum_k h[r][k] * R[k][g]
        unsigned long long a0 = br2, a1 = br2, a2 = br2, a3 = br2;
#pragma unroll 8
        for (int k = 0; k < 128; k++) {
            unsigned long long rv = pack_dup(rp[k * 384]);
            const unsigned long long* hp = (const unsigned long long*)(hT + k * 10);
            ffma2(a0, hp[0], rv);
            ffma2(a1, hp[1], rv);
            ffma2(a2, hp[2], rv);
            ffma2(a3, hp[3], rv);
        }
        {
            float2 f;
            f = unpack2(a0); inn[0 * 384 + tid] = f.x; inn[1 * 384 + tid] = f.y;
            f = unpack2(a1); inn[2 * 384 + tid] = f.x; inn[3 * 384 + tid] = f.y;
            f = unpack2(a2); inn[4 * 384 + tid] = f.x; inn[5 * 384 + tid] = f.y;
            f = unpack2(a3); inn[6 * 384 + tid] = f.x; inn[7 * 384 + tid] = f.y;
        }
        __syncthreads();

        // phase 2: gates + state update + output
#pragma unroll
        for (int s = 0; s < 3; s++) {
            if (s < 2 || tid < 256) {
                int u = uu[s], r = rr_[s];
                float iz  = inn[r * 384 + u];
                float irv = inn[r * 384 + u + 128];
                float ih  = inn[r * 384 + u + 256];
                float z  = sigm(xz[s] + iz);
                float rg = sigm(xr[s] + irv);
                float hh = tanh_fast(xh[s] + rg * ih);
                float hold = hT[u * 10 + r];
                float hn = z * hold + (1.0f - z) * hh;
                bool m = t < lenr[s];
                float hnew = m ? hn : hold;
                hT[u * 10 + r] = hnew;
                float ov = m ? hn : (s == 0 ? po0 : (s == 1 ? po1 : po2));
                if (s == 0) po0 = ov; else if (s == 1) po1 = ov; else po2 = ov;
                out[obase[s] + (size_t)t * U_] = ov;
            }
        }
        __syncthreads();
    }

    // tail: frozen outputs for t >= maxlen (pure stores)
    for (int t = maxlen; t < T_; t++) {
#pragma unroll
        for (int s = 0; s < 3; s++) {
            if (s < 2 || tid < 256) {
                float ov = (s == 0 ? po0 : (s == 1 ? po1 : po2));
                out[obase[s] + (size_t)t * U_] = ov;
            }
        }
    }
}

extern "C" void kernel_launch(void* const* d_in, const int* in_sizes, int n_in,
                              void* d_out, int out_size)
{
    const float* X    = (const float*)d_in[0];   // [B][T][D]
    const int*   slen = (const int*)d_in[1];     // [B][1]
    const float* W    = (const float*)d_in[2];   // [D][3U]
    const float* R    = (const float*)d_in[3];   // [U][3U]
    const float* bias = (const float*)d_in[4];   // [2][3U]
    float* out = (float*)d_out;                  // [B][T][U]

    (void)in_sizes; (void)n_in; (void)out_size;

    const int gemm_smem  = (64 * 128 + 128 * 128) * 4;          // 96 KB
    const int recur_smem = (128 * 384 + 128 * 10 + 8 * 384) * 4; // ~209 KB

    cudaFuncSetAttribute(gemm_in_kernel, cudaFuncAttributeMaxDynamicSharedMemorySize, gemm_smem);
    cudaFuncSetAttribute(recur_kernel,  cudaFuncAttributeMaxDynamicSharedMemorySize, recur_smem);

    sort_rows_kernel<<<1, B_>>>(slen);

    dim3 ggrid(3, 4, B_);
    gemm_in_kernel<<<ggrid, 256, gemm_smem>>>(X, slen, W, bias);

    recur_kernel<<<128, 384, recur_smem>>>(slen, R, bias, out);
}

// round 3
// speedup vs baseline: 1.1898x; 1.1898x over previous
#include <cuda_runtime.h>
#include <cuda_bf16.h>
#include <cstdint>

#define B_ 1024
#define T_ 200
#define D_ 128
#define U_ 128
#define G_ 384   // 3*U

typedef unsigned long long ull;

// Scratch: xm = X@W + b_in, layout [B][T][3U]. Static __device__ (no cudaMalloc allowed).
__device__ float g_xm[(size_t)B_ * T_ * G_];
__device__ int   g_perm[B_];

// ---------- f32x2 helpers ----------
__device__ __forceinline__ ull pack_dup(float x) {
    ull r; asm("mov.b64 %0, {%1, %1};" : "=l"(r) : "f"(x)); return r;
}
__device__ __forceinline__ ull pack2(float x, float y) {
    ull r; asm("mov.b64 %0, {%1, %2};" : "=l"(r) : "f"(x), "f"(y)); return r;
}
__device__ __forceinline__ void ffma2(ull& d, ull a, ull b) {
    asm("fma.rn.f32x2 %0, %1, %2, %0;" : "+l"(d) : "l"(a), "l"(b));
}
__device__ __forceinline__ float2 unpack2(ull v) {
    float2 f; asm("mov.b64 {%0, %1}, %2;" : "=f"(f.x), "=f"(f.y) : "l"(v)); return f;
}

__device__ __forceinline__ float sigm(float x) {
    return __fdividef(1.0f, 1.0f + __expf(-x));
}
__device__ __forceinline__ float tanh_fast(float x) {
    // robust at +-inf
    return 1.0f - __fdividef(2.0f, __expf(2.0f * x) + 1.0f);
}

// ---------- Kernel 0: bitonic sort of batch rows by length (ascending) ----------
__global__ void sort_rows_kernel(const int* __restrict__ slen) {
    __shared__ int key[B_];
    int tid = threadIdx.x;
    key[tid] = slen[tid] * 1024 + tid;   // stable, distinct keys
    __syncthreads();
    for (int size = 2; size <= B_; size <<= 1) {
        for (int stride = size >> 1; stride > 0; stride >>= 1) {
            int j = tid ^ stride;
            if (j > tid) {
                int a = key[tid], b = key[j];
                bool up = (tid & size) == 0;
                if ((a > b) == up) { key[tid] = b; key[j] = a; }
            }
            __syncthreads();
        }
    }
    g_perm[tid] = key[tid] & (B_ - 1);
}

// ---------- Kernel 1: input GEMM xm = X@W + b_in ----------
// Block tile 64 t-rows x 128 cols, 128 threads, 8 rows x 8 cols per thread (FFMA2 over row pairs).
// smem: XsT[128][66] (transposed X) + Wdup[128][128] u64 (each W value duplicated in both lanes).
#define GX_STRIDE 66
__global__ __launch_bounds__(128, 1) void gemm_in_kernel(
    const float* __restrict__ X, const int* __restrict__ slen,
    const float* __restrict__ W, const float* __restrict__ bias)
{
    int b  = blockIdx.z;
    int t0 = blockIdx.y * 64;
    int n0 = blockIdx.x * 128;
    int len = slen[b];
    if (t0 >= len) return;   // xm beyond len never used un-masked

    extern __shared__ float sm[];
    float* XsT = sm;                            // 128 * 66 floats = 33792 B
    ull*   Wd  = (ull*)(sm + 128 * GX_STRIDE);  // 128 * 128 u64   = 131072 B
    int tx = threadIdx.x;

    // X tile -> transposed smem (XsT[d][row])
    const float4* Xg = (const float4*)(X + (size_t)b * T_ * D_);
#pragma unroll
    for (int i = 0; i < 16; i++) {
        int idx = i * 128 + tx;
        int row = idx >> 5;            // 0..63
        int dq  = idx & 31;            // float4 index along D
        int t = t0 + row;
        float4 v = make_float4(0.f, 0.f, 0.f, 0.f);
        if (t < T_) v = Xg[t * 32 + dq];
        int d0 = dq * 4;
        XsT[(d0 + 0) * GX_STRIDE + row] = v.x;
        XsT[(d0 + 1) * GX_STRIDE + row] = v.y;
        XsT[(d0 + 2) * GX_STRIDE + row] = v.z;
        XsT[(d0 + 3) * GX_STRIDE + row] = v.w;
    }
    // W tile -> duplicated-lane smem
#pragma unroll 4
    for (int k = 0; k < 128; k++) {
        float w = W[(size_t)k * G_ + n0 + tx];
        Wd[k * 128 + tx] = pack_dup(w);
    }
    __syncthreads();

    int q  = tx & 15;          // col group: cols {2q,2q+1} + offsets {0,32,64,96}
    int rg = tx >> 4;          // 0..7 -> rows rg*8 .. rg*8+7
    int r0 = rg * 8;

    // acc[c][rp]: c = column index 0..7 -> cols (32*(c/2) + 2q + (c&1)); rp = row pair
    ull acc[8][4];
#pragma unroll
    for (int c = 0; c < 8; c++)
#pragma unroll
        for (int rp = 0; rp < 4; rp++) acc[c][rp] = 0ULL;

#pragma unroll 4
    for (int k = 0; k < 128; k++) {
        const float* xr = XsT + k * GX_STRIDE + r0;
        ull x0 = *(const ull*)(xr);
        ull x1 = *(const ull*)(xr + 2);
        ull x2 = *(const ull*)(xr + 4);
        ull x3 = *(const ull*)(xr + 6);
        const ull* wr = Wd + k * 128 + 2 * q;
        ulonglong2 wA = *(const ulonglong2*)(wr);        // cols 2q, 2q+1
        ulonglong2 wB = *(const ulonglong2*)(wr + 32);   // cols 32+2q, 33+2q
        ulonglong2 wC = *(const ulonglong2*)(wr + 64);   // cols 64+2q, 65+2q
        ulonglong2 wD = *(const ulonglong2*)(wr + 96);   // cols 96+2q, 97+2q
        ffma2(acc[0][0], x0, wA.x); ffma2(acc[0][1], x1, wA.x); ffma2(acc[0][2], x2, wA.x); ffma2(acc[0][3], x3, wA.x);
        ffma2(acc[1][0], x0, wA.y); ffma2(acc[1][1], x1, wA.y); ffma2(acc[1][2], x2, wA.y); ffma2(acc[1][3], x3, wA.y);
        ffma2(acc[2][0], x0, wB.x); ffma2(acc[2][1], x1, wB.x); ffma2(acc[2][2], x2, wB.x); ffma2(acc[2][3], x3, wB.x);
        ffma2(acc[3][0], x0, wB.y); ffma2(acc[3][1], x1, wB.y); ffma2(acc[3][2], x2, wB.y); ffma2(acc[3][3], x3, wB.y);
        ffma2(acc[4][0], x0, wC.x); ffma2(acc[4][1], x1, wC.x); ffma2(acc[4][2], x2, wC.x); ffma2(acc[4][3], x3, wC.x);
        ffma2(acc[5][0], x0, wC.y); ffma2(acc[5][1], x1, wC.y); ffma2(acc[5][2], x2, wC.y); ffma2(acc[5][3], x3, wC.y);
        ffma2(acc[6][0], x0, wD.x); ffma2(acc[6][1], x1, wD.x); ffma2(acc[6][2], x2, wD.x); ffma2(acc[6][3], x3, wD.x);
        ffma2(acc[7][0], x0, wD.y); ffma2(acc[7][1], x1, wD.y); ffma2(acc[7][2], x2, wD.y); ffma2(acc[7][3], x3, wD.y);
    }

    // epilogue: bias + store (float2 per col-pair)
    float2 bA = make_float2(bias[n0 + 2*q],      bias[n0 + 2*q + 1]);
    float2 bB = make_float2(bias[n0 + 32 + 2*q], bias[n0 + 33 + 2*q]);
    float2 bC = make_float2(bias[n0 + 64 + 2*q], bias[n0 + 65 + 2*q]);
    float2 bD = make_float2(bias[n0 + 96 + 2*q], bias[n0 + 97 + 2*q]);

#pragma unroll
    for (int rp = 0; rp < 4; rp++) {
        float2 c0 = unpack2(acc[0][rp]);
        float2 c1 = unpack2(acc[1][rp]);
        float2 c2 = unpack2(acc[2][rp]);
        float2 c3 = unpack2(acc[3][rp]);
        float2 c4 = unpack2(acc[4][rp]);
        float2 c5 = unpack2(acc[5][rp]);
        float2 c6 = unpack2(acc[6][rp]);
        float2 c7 = unpack2(acc[7][rp]);
#pragma unroll
        for (int e = 0; e < 2; e++) {
            int t = t0 + r0 + 2 * rp + e;
            if (t >= T_) continue;
            float* op = g_xm + ((size_t)b * T_ + t) * G_ + n0;
            float a0 = e ? c0.y : c0.x, a1 = e ? c1.y : c1.x;
            float a2 = e ? c2.y : c2.x, a3 = e ? c3.y : c3.x;
            float a4 = e ? c4.y : c4.x, a5 = e ? c5.y : c5.x;
            float a6 = e ? c6.y : c6.x, a7 = e ? c7.y : c7.x;
            *(float2*)(op + 2*q)      = make_float2(a0 + bA.x, a1 + bA.y);
            *(float2*)(op + 32 + 2*q) = make_float2(a2 + bB.x, a3 + bB.y);
            *(float2*)(op + 64 + 2*q) = make_float2(a4 + bC.x, a5 + bC.y);
            *(float2*)(op + 96 + 2*q) = make_float2(a6 + bD.x, a7 + bD.y);
        }
    }
}

// ---------- Kernel 2: recurrence, thread-owns-unit ----------
// 256 blocks x 4 rows (sorted desc), 128 threads; thread u owns gates (u, u+128, u+256).
// smem: Rzr[k][u] u64 pairs (Rz,Rr) 128KB + Rh[k][u] 64KB + h double-buffer (dup pairs) 8KB.
__global__ __launch_bounds__(128, 1) void recur_kernel(
    const int* __restrict__ slen, const float* __restrict__ R,
    const float* __restrict__ bias, float* __restrict__ out)
{
    extern __shared__ float sm[];
    ull*   Rzr = (ull*)sm;                       // [128][128] u64
    float* Rh  = (float*)(Rzr + 128 * 128);      // [128][128] float
    ull*   hd  = (ull*)(Rh + 128 * 128);         // [2][128][4] u64 (dup pairs)
    __shared__ int rows_s[4], len_s[4];

    int u = threadIdx.x;   // 0..127 = hidden unit

    // pack R into smem: Rzr[k][u] = (R[k][u], R[k][u+128]), Rh[k][u] = R[k][u+256]
#pragma unroll 4
    for (int k = 0; k < 128; k++) {
        const float* rrow = R + (size_t)k * G_;
        Rzr[k * 128 + u] = pack2(rrow[u], rrow[u + 128]);
        Rh[k * 128 + u]  = rrow[u + 256];
    }
    if (u < 4) {
        int idx = B_ - 1 - (blockIdx.x * 4 + u);   // descending lengths
        int row = g_perm[idx];
        rows_s[u] = row;
        len_s[u]  = slen[row];
    }
    for (int i = u; i < 2 * 128 * 4; i += 128) hd[i] = 0ULL;
    __syncthreads();

    int len0 = len_s[0], len1 = len_s[1], len2 = len_s[2], len3 = len_s[3];
    int maxlen = max(max(len0, len1), max(len2, len3));

    const float* xb0 = g_xm + (size_t)rows_s[0] * T_ * G_ + u;
    const float* xb1 = g_xm + (size_t)rows_s[1] * T_ * G_ + u;
    const float* xb2 = g_xm + (size_t)rows_s[2] * T_ * G_ + u;
    const float* xb3 = g_xm + (size_t)rows_s[3] * T_ * G_ + u;
    float* ob0 = out + (size_t)rows_s[0] * T_ * U_ + u;
    float* ob1 = out + (size_t)rows_s[1] * T_ * U_ + u;
    float* ob2 = out + (size_t)rows_s[2] * T_ * U_ + u;
    float* ob3 = out + (size_t)rows_s[3] * T_ * U_ + u;

    ull brzr = pack2(bias[G_ + u], bias[G_ + u + 128]);
    ull brh  = pack_dup(bias[G_ + u + 256]);

    float h0 = 0.f, h1 = 0.f, h2 = 0.f, h3 = 0.f;
    float po0 = 0.f, po1 = 0.f, po2 = 0.f, po3 = 0.f;

    const ull*   Rzr_u = Rzr + u;
    const float* Rh_u  = Rh + u;

    for (int t = 0; t < maxlen; t++) {
        // prefetch xm for this step (hidden behind the matmul)
        size_t toff = (size_t)t * G_;
        float xz0 = xb0[toff], xr0 = xb0[toff + 128], xh0 = xb0[toff + 256];
        float xz1 = xb1[toff], xr1 = xb1[toff + 128], xh1 = xb1[toff + 256];
        float xz2 = xb2[toff], xr2 = xb2[toff + 128], xh2 = xb2[toff + 256];
        float xz3 = xb3[toff], xr3 = xb3[toff + 128], xh3 = xb3[toff + 256];

        const ull* hc = hd + (t & 1) * 512;
        ull az0 = brzr, az1 = brzr, az2 = brzr, az3 = brzr;   // (z,r) gate pairs per row
        ull ah0 = brh,  ah1 = brh,  ah2 = brh,  ah3 = brh;    // h gate (dup lanes)

#pragma unroll 8
        for (int k = 0; k < 128; k++) {
            ulonglong2 hA = *(const ulonglong2*)(hc + k * 4);      // rows 0,1 (dup)
            ulonglong2 hB = *(const ulonglong2*)(hc + k * 4 + 2);  // rows 2,3 (dup)
            ull rzr = Rzr_u[k * 128];
            ull rh2 = pack_dup(Rh_u[k * 128]);
            ffma2(az0, hA.x, rzr);
            ffma2(az1, hA.y, rzr);
            ffma2(az2, hB.x, rzr);
            ffma2(az3, hB.y, rzr);
            ffma2(ah0, hA.x, rh2);
            ffma2(ah1, hA.y, rh2);
            ffma2(ah2, hB.x, rh2);
            ffma2(ah3, hB.y, rh2);
        }

        ull* hn = hd + ((t + 1) & 1) * 512;

        // gates + state update, all in registers
        {
            float2 a = unpack2(az0); float ih = unpack2(ah0).x;
            float z = sigm(xz0 + a.x), r = sigm(xr0 + a.y);
            float hh = tanh_fast(xh0 + r * ih);
            float v = z * h0 + (1.0f - z) * hh;
            bool m = t < len0;
            h0 = m ? v : h0; po0 = m ? v : po0;
            ob0[(size_t)t * U_] = po0;
        }
        {
            float2 a = unpack2(az1); float ih = unpack2(ah1).x;
            float z = sigm(xz1 + a.x), r = sigm(xr1 + a.y);
            float hh = tanh_fast(xh1 + r * ih);
            float v = z * h1 + (1.0f - z) * hh;
            bool m = t < len1;
            h1 = m ? v : h1; po1 = m ? v : po1;
            ob1[(size_t)t * U_] = po1;
        }
        {
            float2 a = unpack2(az2); float ih = unpack2(ah2).x;
            float z = sigm(xz2 + a.x), r = sigm(xr2 + a.y);
            float hh = tanh_fast(xh2 + r * ih);
            float v = z * h2 + (1.0f - z) * hh;
            bool m = t < len2;
            h2 = m ? v : h2; po2 = m ? v : po2;
            ob2[(size_t)t * U_] = po2;
        }
        {
            float2 a = unpack2(az3); float ih = unpack2(ah3).x;
            float z = sigm(xz3 + a.x), r = sigm(xr3 + a.y);
            float hh = tanh_fast(xh3 + r * ih);
            float v = z * h3 + (1.0f - z) * hh;
            bool m = t < len3;
            h3 = m ? v : h3; po3 = m ? v : po3;
            ob3[(size_t)t * U_] = po3;
        }
        // publish next-step h (duplicated pairs) into the other buffer
        {
            uint4 w0, w1;
            w0.x = __float_as_uint(h0); w0.y = w0.x;
            w0.z = __float_as_uint(h1); w0.w = w0.z;
            w1.x = __float_as_uint(h2); w1.y = w1.x;
            w1.z = __float_as_uint(h3); w1.w = w1.z;
            *(uint4*)(hn + u * 4)     = w0;
            *(uint4*)(hn + u * 4 + 2) = w1;
        }
        __syncthreads();
    }

    // tail: frozen outputs (pure stores)
    for (int t = maxlen; t < T_; t++) {
        ob0[(size_t)t * U_] = po0;
        ob1[(size_t)t * U_] = po1;
        ob2[(size_t)t * U_] = po2;
        ob3[(size_t)t * U_] = po3;
    }
}

extern "C" void kernel_launch(void* const* d_in, const int* in_sizes, int n_in,
                              void* d_out, int out_size)
{
    const float* X    = (const float*)d_in[0];   // [B][T][D]
    const int*   slen = (const int*)d_in[1];     // [B][1]
    const float* W    = (const float*)d_in[2];   // [D][3U]
    const float* R    = (const float*)d_in[3];   // [U][3U]
    const float* bias = (const float*)d_in[4];   // [2][3U]
    float* out = (float*)d_out;                  // [B][T][U]

    (void)in_sizes; (void)n_in; (void)out_size;

    const int gemm_smem  = 128 * GX_STRIDE * 4 + 128 * 128 * 8;              // 164864 B
    const int recur_smem = 128 * 128 * 8 + 128 * 128 * 4 + 2 * 128 * 4 * 8;  // 204800 B

    cudaFuncSetAttribute(gemm_in_kernel, cudaFuncAttributeMaxDynamicSharedMemorySize, gemm_smem);
    cudaFuncSetAttribute(recur_kernel,  cudaFuncAttributeMaxDynamicSharedMemorySize, recur_smem);

    sort_rows_kernel<<<1, B_>>>(slen);

    dim3 ggrid(3, 4, B_);   // 3 col-tiles of 128, 4 t-tiles of 64, B
    gemm_in_kernel<<<ggrid, 128, gemm_smem>>>(X, slen, W, bias);

    recur_kernel<<<256, 128, recur_smem>>>(slen, R, bias, out);
}

// round 4
// speedup vs baseline: 1.3481x; 1.1331x over previous
#include <cuda_runtime.h>
#include <cuda_bf16.h>
#include <cstdint>

#define B_ 1024
#define T_ 200
#define D_ 128
#define U_ 128
#define G_ 384   // 3*U

typedef unsigned long long ull;

// Scratch: xm = X@W + b_in, layout [B][T][3U]. Static __device__ (no cudaMalloc allowed).
__device__ float g_xm[(size_t)B_ * T_ * G_];
__device__ int   g_perm[B_];

// ---------- f32x2 helpers ----------
__device__ __forceinline__ ull pack_dup(float x) {
    ull r; asm("mov.b64 %0, {%1, %1};" : "=l"(r) : "f"(x)); return r;
}
__device__ __forceinline__ ull pack2(float x, float y) {
    ull r; asm("mov.b64 %0, {%1, %2};" : "=l"(r) : "f"(x), "f"(y)); return r;
}
__device__ __forceinline__ void ffma2(ull& d, ull a, ull b) {
    asm("fma.rn.f32x2 %0, %1, %2, %0;" : "+l"(d) : "l"(a), "l"(b));
}
__device__ __forceinline__ float2 unpack2(ull v) {
    float2 f; asm("mov.b64 {%0, %1}, %2;" : "=f"(f.x), "=f"(f.y) : "l"(v)); return f;
}

__device__ __forceinline__ float sigm(float x) {
    return __fdividef(1.0f, 1.0f + __expf(-x));
}
__device__ __forceinline__ float tanh_fast(float x) {
    return 1.0f - __fdividef(2.0f, __expf(2.0f * x) + 1.0f);
}

// ---------- Kernel 0: bitonic sort of batch rows by length (ascending) ----------
__global__ void sort_rows_kernel(const int* __restrict__ slen) {
    __shared__ int key[B_];
    int tid = threadIdx.x;
    key[tid] = slen[tid] * 1024 + tid;   // stable, distinct keys
    __syncthreads();
    for (int size = 2; size <= B_; size <<= 1) {
        for (int stride = size >> 1; stride > 0; stride >>= 1) {
            int j = tid ^ stride;
            if (j > tid) {
                int a = key[tid], b = key[j];
                bool up = (tid & size) == 0;
                if ((a > b) == up) { key[tid] = b; key[j] = a; }
            }
            __syncthreads();
        }
    }
    g_perm[tid] = key[tid] & (B_ - 1);
}

// ---------- Kernel 1: input GEMM xm = X@W + b_in ----------
// Block tile 64 t-rows x 128 cols, 128 threads, 8 rows x 8 cols per thread.
// smem: XsT[128][66] (transposed X) + Wdup[128][128] u64 (duplicated-lane W).
#define GX_STRIDE 66
__global__ __launch_bounds__(128, 1) void gemm_in_kernel(
    const float* __restrict__ X, const int* __restrict__ slen,
    const float* __restrict__ W, const float* __restrict__ bias)
{
    int b  = blockIdx.z;
    int t0 = blockIdx.y * 64;
    int n0 = blockIdx.x * 128;
    int len = slen[b];
    if (t0 >= len) return;   // xm beyond len never used un-masked

    extern __shared__ float sm[];
    float* XsT = sm;                            // 128 * 66 floats = 33792 B
    ull*   Wd  = (ull*)(sm + 128 * GX_STRIDE);  // 128 * 128 u64   = 131072 B
    int tx = threadIdx.x;

    // X tile -> transposed smem (XsT[d][row]); 16 independent LDG.128/thread
    const float4* Xg = (const float4*)(X + (size_t)b * T_ * D_);
#pragma unroll
    for (int i = 0; i < 16; i++) {
        int idx = i * 128 + tx;
        int row = idx >> 5;            // 0..63
        int dq  = idx & 31;            // float4 index along D
        int t = t0 + row;
        float4 v = make_float4(0.f, 0.f, 0.f, 0.f);
        if (t < T_) v = Xg[t * 32 + dq];
        int d0 = dq * 4;
        XsT[(d0 + 0) * GX_STRIDE + row] = v.x;
        XsT[(d0 + 1) * GX_STRIDE + row] = v.y;
        XsT[(d0 + 2) * GX_STRIDE + row] = v.z;
        XsT[(d0 + 3) * GX_STRIDE + row] = v.w;
    }
    // W tile -> duplicated-lane smem; 32 independent LDG.128/thread (high MLP)
#pragma unroll
    for (int i = 0; i < 32; i++) {
        int idx = i * 128 + tx;        // 0..4095 float4s of the 128x128 tile
        int k  = idx >> 5;
        int cq = idx & 31;
        float4 v = *(const float4*)(W + (size_t)k * G_ + n0 + cq * 4);
        ull* dst = Wd + k * 128 + cq * 4;
        ulonglong2 d0; d0.x = pack_dup(v.x); d0.y = pack_dup(v.y);
        ulonglong2 d1; d1.x = pack_dup(v.z); d1.y = pack_dup(v.w);
        *(ulonglong2*)(dst)     = d0;
        *(ulonglong2*)(dst + 2) = d1;
    }
    __syncthreads();

    int q  = tx & 15;          // col group: cols {2q,2q+1} + offsets {0,32,64,96}
    int rg = tx >> 4;          // 0..7 -> rows rg*8 .. rg*8+7
    int r0 = rg * 8;

    ull acc[8][4];
#pragma unroll
    for (int c = 0; c < 8; c++)
#pragma unroll
        for (int rp = 0; rp < 4; rp++) acc[c][rp] = 0ULL;

#pragma unroll 4
    for (int k = 0; k < 128; k++) {
        const float* xr = XsT + k * GX_STRIDE + r0;
        ull x0 = *(const ull*)(xr);
        ull x1 = *(const ull*)(xr + 2);
        ull x2 = *(const ull*)(xr + 4);
        ull x3 = *(const ull*)(xr + 6);
        const ull* wr = Wd + k * 128 + 2 * q;
        ulonglong2 wA = *(const ulonglong2*)(wr);        // cols 2q, 2q+1
        ulonglong2 wB = *(const ulonglong2*)(wr + 32);   // cols 32+2q, 33+2q
        ulonglong2 wC = *(const ulonglong2*)(wr + 64);   // cols 64+2q, 65+2q
        ulonglong2 wD = *(const ulonglong2*)(wr + 96);   // cols 96+2q, 97+2q
        ffma2(acc[0][0], x0, wA.x); ffma2(acc[0][1], x1, wA.x); ffma2(acc[0][2], x2, wA.x); ffma2(acc[0][3], x3, wA.x);
        ffma2(acc[1][0], x0, wA.y); ffma2(acc[1][1], x1, wA.y); ffma2(acc[1][2], x2, wA.y); ffma2(acc[1][3], x3, wA.y);
        ffma2(acc[2][0], x0, wB.x); ffma2(acc[2][1], x1, wB.x); ffma2(acc[2][2], x2, wB.x); ffma2(acc[2][3], x3, wB.x);
        ffma2(acc[3][0], x0, wB.y); ffma2(acc[3][1], x1, wB.y); ffma2(acc[3][2], x2, wB.y); ffma2(acc[3][3], x3, wB.y);
        ffma2(acc[4][0], x0, wC.x); ffma2(acc[4][1], x1, wC.x); ffma2(acc[4][2], x2, wC.x); ffma2(acc[4][3], x3, wC.x);
        ffma2(acc[5][0], x0, wC.y); ffma2(acc[5][1], x1, wC.y); ffma2(acc[5][2], x2, wC.y); ffma2(acc[5][3], x3, wC.y);
        ffma2(acc[6][0], x0, wD.x); ffma2(acc[6][1], x1, wD.x); ffma2(acc[6][2], x2, wD.x); ffma2(acc[6][3], x3, wD.x);
        ffma2(acc[7][0], x0, wD.y); ffma2(acc[7][1], x1, wD.y); ffma2(acc[7][2], x2, wD.y); ffma2(acc[7][3], x3, wD.y);
    }

    // epilogue: bias + store (float2 per col-pair)
    float2 bA = make_float2(bias[n0 + 2*q],      bias[n0 + 2*q + 1]);
    float2 bB = make_float2(bias[n0 + 32 + 2*q], bias[n0 + 33 + 2*q]);
    float2 bC = make_float2(bias[n0 + 64 + 2*q], bias[n0 + 65 + 2*q]);
    float2 bD = make_float2(bias[n0 + 96 + 2*q], bias[n0 + 97 + 2*q]);

#pragma unroll
    for (int rp = 0; rp < 4; rp++) {
        float2 c0 = unpack2(acc[0][rp]);
        float2 c1 = unpack2(acc[1][rp]);
        float2 c2 = unpack2(acc[2][rp]);
        float2 c3 = unpack2(acc[3][rp]);
        float2 c4 = unpack2(acc[4][rp]);
        float2 c5 = unpack2(acc[5][rp]);
        float2 c6 = unpack2(acc[6][rp]);
        float2 c7 = unpack2(acc[7][rp]);
#pragma unroll
        for (int e = 0; e < 2; e++) {
            int t = t0 + r0 + 2 * rp + e;
            if (t >= T_) continue;
            float* op = g_xm + ((size_t)b * T_ + t) * G_ + n0;
            float a0 = e ? c0.y : c0.x, a1 = e ? c1.y : c1.x;
            float a2 = e ? c2.y : c2.x, a3 = e ? c3.y : c3.x;
            float a4 = e ? c4.y : c4.x, a5 = e ? c5.y : c5.x;
            float a6 = e ? c6.y : c6.x, a7 = e ? c7.y : c7.x;
            *(float2*)(op + 2*q)      = make_float2(a0 + bA.x, a1 + bA.y);
            *(float2*)(op + 32 + 2*q) = make_float2(a2 + bB.x, a3 + bB.y);
            *(float2*)(op + 64 + 2*q) = make_float2(a4 + bC.x, a5 + bC.y);
            *(float2*)(op + 96 + 2*q) = make_float2(a6 + bD.x, a7 + bD.y);
        }
    }
}

// ---------- Kernel 2: recurrence, thread-owns-unit, paired h-gate ----------
// 256 blocks x 4 rows (sorted desc), 128 threads; thread u owns gates (u, u+128, u+256).
// Per k: 6 FFMA2 (4x (z,r)-pair with dup-h, 2x h-gate with row-paired h).
// smem: Rzr2 [64][128] ulonglong2 (k-paired (Rz,Rr)) 128KB
//       Rh2  [64][128] float2 (k-paired Rh)           64KB
//       hd   [2][128][4] ull dup pairs                 8KB
//       hp   [2][128][2] ull row pairs                 4KB
__global__ __launch_bounds__(128, 1) void recur_kernel(
    const int* __restrict__ slen, const float* __restrict__ R,
    const float* __restrict__ bias, float* __restrict__ out)
{
    extern __shared__ char smraw[];
    ull*    Rzr2 = (ull*)smraw;                          // [64][128][2] ull
    float2* Rh2  = (float2*)(smraw + 131072);            // [64][128]
    ull*    hd   = (ull*)(smraw + 131072 + 65536);       // [2][128][4]
    ull*    hp   = (ull*)(smraw + 131072 + 65536 + 8192);// [2][128][2]
    __shared__ int rows_s[4], len_s[4];

    int u = threadIdx.x;   // 0..127 = hidden unit

    // ---- R fill: 96 independent LDG.128/thread, scatter to packed layout ----
    {
        const float4* R4 = (const float4*)R;   // 12288 float4s
#pragma unroll 8
        for (int i = 0; i < 96; i++) {
            int f = i * 128 + u;
            float4 v = R4[f];
            int k = f / 96;               // row of R
            int c = (f - k * 96) * 4;     // col 0..380, never crosses gate boundary
            int kk = k >> 1, kp = k & 1;
            if (c < 128) {
                float* dst = (float*)&Rzr2[(kk * 128 + c) * 2 + kp];     // rz lane
                dst[0] = v.x; dst[4] = v.y; dst[8] = v.z; dst[12] = v.w;
            } else if (c < 256) {
                float* dst = (float*)&Rzr2[(kk * 128 + (c - 128)) * 2 + kp] + 1; // rr lane
                dst[0] = v.x; dst[4] = v.y; dst[8] = v.z; dst[12] = v.w;
            } else {
                float* dst = (float*)&Rh2[kk * 128 + (c - 256)] + kp;
                dst[0] = v.x; dst[2] = v.y; dst[4] = v.z; dst[6] = v.w;
            }
        }
    }
    if (u < 4) {
        int idx = B_ - 1 - (blockIdx.x * 4 + u);   // descending lengths
        int row = g_perm[idx];
        rows_s[u] = row;
        len_s[u]  = slen[row];
    }
    // zero both h buffers
    for (int i = u; i < 2 * 128 * 4; i += 128) hd[i] = 0ULL;
    for (int i = u; i < 2 * 128 * 2; i += 128) hp[i] = 0ULL;
    __syncthreads();

    int len0 = len_s[0], len1 = len_s[1], len2 = len_s[2], len3 = len_s[3];
    int maxlen = max(max(len0, len1), max(len2, len3));

    const float* xb0 = g_xm + (size_t)rows_s[0] * T_ * G_ + u;
    const float* xb1 = g_xm + (size_t)rows_s[1] * T_ * G_ + u;
    const float* xb2 = g_xm + (size_t)rows_s[2] * T_ * G_ + u;
    const float* xb3 = g_xm + (size_t)rows_s[3] * T_ * G_ + u;
    float* ob0 = out + (size_t)rows_s[0] * T_ * U_ + u;
    float* ob1 = out + (size_t)rows_s[1] * T_ * U_ + u;
    float* ob2 = out + (size_t)rows_s[2] * T_ * U_ + u;
    float* ob3 = out + (size_t)rows_s[3] * T_ * U_ + u;

    ull brzr = pack2(bias[G_ + u], bias[G_ + u + 128]);
    ull brh  = pack_dup(bias[G_ + u + 256]);

    float h0 = 0.f, h1 = 0.f, h2 = 0.f, h3 = 0.f;
    float po0 = 0.f, po1 = 0.f, po2 = 0.f, po3 = 0.f;

    const ull*    Rp  = Rzr2 + u * 2;   // stride 256 ull per kk
    const float2* Rhp = Rh2 + u;        // stride 128 per kk

    for (int t = 0; t < maxlen; t++) {
        // prefetch xm for this step (12 independent LDGs, hidden behind matmul)
        size_t toff = (size_t)t * G_;
        float xz0 = xb0[toff], xr0 = xb0[toff + 128], xh0 = xb0[toff + 256];
        float xz1 = xb1[toff], xr1 = xb1[toff + 128], xh1 = xb1[toff + 256];
        float xz2 = xb2[toff], xr2 = xb2[toff + 128], xh2 = xb2[toff + 256];
        float xz3 = xb3[toff], xr3 = xb3[toff + 128], xh3 = xb3[toff + 256];

        const ull* hc  = hd + (t & 1) * 512;
        const ull* hpc = hp + (t & 1) * 256;
        ull az0 = brzr, az1 = brzr, az2 = brzr, az3 = brzr;  // (z,r) per row
        ull ah01 = brh, ah23 = brh;                          // h gate, row pairs

#pragma unroll 4
        for (int kk = 0; kk < 64; kk++) {
            ulonglong2 rzr2 = *(const ulonglong2*)(Rp + kk * 256);
            float2 rh2v = Rhp[kk * 128];
            const ull* hck = hc + kk * 8;
            ulonglong2 hA0 = *(const ulonglong2*)(hck);       // k=2kk rows 0,1 dup
            ulonglong2 hB0 = *(const ulonglong2*)(hck + 2);   // k=2kk rows 2,3 dup
            ulonglong2 hA1 = *(const ulonglong2*)(hck + 4);   // k=2kk+1
            ulonglong2 hB1 = *(const ulonglong2*)(hck + 6);
            const ull* hpk = hpc + kk * 4;
            ulonglong2 hp0 = *(const ulonglong2*)(hpk);       // k=2kk: (h0,h1),(h2,h3)
            ulonglong2 hp1 = *(const ulonglong2*)(hpk + 2);   // k=2kk+1
            ull rh0 = pack_dup(rh2v.x);
            ull rh1 = pack_dup(rh2v.y);
            ffma2(az0, hA0.x, rzr2.x); ffma2(az1, hA0.y, rzr2.x);
            ffma2(az2, hB0.x, rzr2.x); ffma2(az3, hB0.y, rzr2.x);
            ffma2(ah01, hp0.x, rh0);   ffma2(ah23, hp0.y, rh0);
            ffma2(az0, hA1.x, rzr2.y); ffma2(az1, hA1.y, rzr2.y);
            ffma2(az2, hB1.x, rzr2.y); ffma2(az3, hB1.y, rzr2.y);
            ffma2(ah01, hp1.x, rh1);   ffma2(ah23, hp1.y, rh1);
        }

        float2 ap01 = unpack2(ah01);   // h-gate pre-acts rows 0,1
        float2 ap23 = unpack2(ah23);   // rows 2,3

        // gates + state update, all in registers
        {
            float2 a = unpack2(az0);
            float z = sigm(xz0 + a.x), r = sigm(xr0 + a.y);
            float hh = tanh_fast(xh0 + r * ap01.x);
            float v = z * h0 + (1.0f - z) * hh;
            bool m = t < len0;
            h0 = m ? v : h0; po0 = m ? v : po0;
            ob0[(size_t)t * U_] = po0;
        }
        {
            float2 a = unpack2(az1);
            float z = sigm(xz1 + a.x), r = sigm(xr1 + a.y);
            float hh = tanh_fast(xh1 + r * ap01.y);
            float v = z * h1 + (1.0f - z) * hh;
            bool m = t < len1;
            h1 = m ? v : h1; po1 = m ? v : po1;
            ob1[(size_t)t * U_] = po1;
        }
        {
            float2 a = unpack2(az2);
            float z = sigm(xz2 + a.x), r = sigm(xr2 + a.y);
            float hh = tanh_fast(xh2 + r * ap23.x);
            float v = z * h2 + (1.0f - z) * hh;
            bool m = t < len2;
            h2 = m ? v : h2; po2 = m ? v : po2;
            ob2[(size_t)t * U_] = po2;
        }
        {
            float2 a = unpack2(az3);
            float z = sigm(xz3 + a.x), r = sigm(xr3 + a.y);
            float hh = tanh_fast(xh3 + r * ap23.y);
            float v = z * h3 + (1.0f - z) * hh;
            bool m = t < len3;
            h3 = m ? v : h3; po3 = m ? v : po3;
            ob3[(size_t)t * U_] = po3;
        }
        // publish next-step h: dup pairs + row pairs
        {
            ull* hdn = hd + ((t + 1) & 1) * 512;
            ull* hpn = hp + ((t + 1) & 1) * 256;
            uint4 w0, w1, wp;
            w0.x = __float_as_uint(h0); w0.y = w0.x;
            w0.z = __float_as_uint(h1); w0.w = w0.z;
            w1.x = __float_as_uint(h2); w1.y = w1.x;
            w1.z = __float_as_uint(h3); w1.w = w1.z;
            wp.x = __float_as_uint(h0); wp.y = __float_as_uint(h1);
            wp.z = __float_as_uint(h2); wp.w = __float_as_uint(h3);
            *(uint4*)(hdn + u * 4)     = w0;
            *(uint4*)(hdn + u * 4 + 2) = w1;
            *(uint4*)(hpn + u * 2)     = wp;
        }
        __syncthreads();
    }

    // tail: frozen outputs (pure stores)
    for (int t = maxlen; t < T_; t++) {
        ob0[(size_t)t * U_] = po0;
        ob1[(size_t)t * U_] = po1;
        ob2[(size_t)t * U_] = po2;
        ob3[(size_t)t * U_] = po3;
    }
}

extern "C" void kernel_launch(void* const* d_in, const int* in_sizes, int n_in,
                              void* d_out, int out_size)
{
    const float* X    = (const float*)d_in[0];   // [B][T][D]
    const int*   slen = (const int*)d_in[1];     // [B][1]
    const float* W    = (const float*)d_in[2];   // [D][3U]
    const float* R    = (const float*)d_in[3];   // [U][3U]
    const float* bias = (const float*)d_in[4];   // [2][3U]
    float* out = (float*)d_out;                  // [B][T][U]

    (void)in_sizes; (void)n_in; (void)out_size;

    const int gemm_smem  = 128 * GX_STRIDE * 4 + 128 * 128 * 8;   // 164864 B
    const int recur_smem = 131072 + 65536 + 8192 + 4096;          // 208896 B

    cudaFuncSetAttribute(gemm_in_kernel, cudaFuncAttributeMaxDynamicSharedMemorySize, gemm_smem);
    cudaFuncSetAttribute(recur_kernel,  cudaFuncAttributeMaxDynamicSharedMemorySize, recur_smem);

    sort_rows_kernel<<<1, B_>>>(slen);

    dim3 ggrid(3, 4, B_);   // 3 col-tiles of 128, 4 t-tiles of 64, B
    gemm_in_kernel<<<ggrid, 128, gemm_smem>>>(X, slen, W, bias);

    recur_kernel<<<256, 128, recur_smem>>>(slen, R, bias, out);
}

// round 5
// speedup vs baseline: 1.5433x; 1.1448x over previous
#include <cuda_runtime.h>
#include <cuda_bf16.h>
#include <cstdint>

#define B_ 1024
#define T_ 200
#define D_ 128
#define U_ 128
#define G_ 384   // 3*U

typedef unsigned long long ull;

// Scratch: xm = X@W + b_in, layout [B][T][3U]. Static __device__ (no cudaMalloc allowed).
__device__ float g_xm[(size_t)B_ * T_ * G_];
__device__ int   g_perm[B_];

// ---------- f32x2 helpers ----------
__device__ __forceinline__ ull pack_dup(float x) {
    ull r; asm("mov.b64 %0, {%1, %1};" : "=l"(r) : "f"(x)); return r;
}
__device__ __forceinline__ ull pack2(float x, float y) {
    ull r; asm("mov.b64 %0, {%1, %2};" : "=l"(r) : "f"(x), "f"(y)); return r;
}
__device__ __forceinline__ void ffma2(ull& d, ull a, ull b) {
    asm("fma.rn.f32x2 %0, %1, %2, %0;" : "+l"(d) : "l"(a), "l"(b));
}
__device__ __forceinline__ ull addf2(ull a, ull b) {
    ull r; asm("add.rn.f32x2 %0, %1, %2;" : "=l"(r) : "l"(a), "l"(b)); return r;
}
__device__ __forceinline__ float2 unpack2(ull v) {
    float2 f; asm("mov.b64 {%0, %1}, %2;" : "=f"(f.x), "=f"(f.y) : "l"(v)); return f;
}

__device__ __forceinline__ float sigm(float x) {
    return __fdividef(1.0f, 1.0f + __expf(-x));
}
__device__ __forceinline__ float tanh_fast(float x) {
    return 1.0f - __fdividef(2.0f, __expf(2.0f * x) + 1.0f);
}

// ---------- Kernel 0: bitonic sort of batch rows by length (ascending) ----------
__global__ void sort_rows_kernel(const int* __restrict__ slen) {
    __shared__ int key[B_];
    int tid = threadIdx.x;
    key[tid] = slen[tid] * 1024 + tid;   // stable, distinct keys
    __syncthreads();
    for (int size = 2; size <= B_; size <<= 1) {
        for (int stride = size >> 1; stride > 0; stride >>= 1) {
            int j = tid ^ stride;
            if (j > tid) {
                int a = key[tid], b = key[j];
                bool up = (tid & size) == 0;
                if ((a > b) == up) { key[tid] = b; key[j] = a; }
            }
            __syncthreads();
        }
    }
    g_perm[tid] = key[tid] & (B_ - 1);
}

// ---------- Kernel 1: input GEMM xm = X@W + b_in ----------
// Block tile 64 t-rows x 128 cols, 128 threads, 2 blocks/SM (99KB smem).
// Thread tile: 4 rows x 16 cols (4 spread quads). W natural in smem (col-pairs in lanes),
// X duplicated in registers (4 movs/k).
#define GX_STRIDE 66
__global__ __launch_bounds__(128, 2) void gemm_in_kernel(
    const float* __restrict__ X, const int* __restrict__ slen,
    const float* __restrict__ W, const float* __restrict__ bias)
{
    int b  = blockIdx.z;
    int t0 = blockIdx.y * 64;
    int n0 = blockIdx.x * 128;
    int len = slen[b];
    if (t0 >= len) return;   // xm beyond len never used un-masked

    extern __shared__ float sm[];
    float* XsT = sm;                            // [128][66]  = 33792 B
    ull*   Ws  = (ull*)(sm + 128 * GX_STRIDE);  // [128][64]  = 65536 B
    int tx = threadIdx.x;

    // X tile -> transposed smem (XsT[d][row]); 16 independent LDG.128/thread
    const float4* Xg = (const float4*)(X + (size_t)b * T_ * D_);
#pragma unroll
    for (int i = 0; i < 16; i++) {
        int idx = i * 128 + tx;
        int row = idx >> 5;            // 0..63
        int dq  = idx & 31;            // float4 index along D
        int t = t0 + row;
        float4 v = make_float4(0.f, 0.f, 0.f, 0.f);
        if (t < T_) v = Xg[t * 32 + dq];
        int d0 = dq * 4;
        XsT[(d0 + 0) * GX_STRIDE + row] = v.x;
        XsT[(d0 + 1) * GX_STRIDE + row] = v.y;
        XsT[(d0 + 2) * GX_STRIDE + row] = v.z;
        XsT[(d0 + 3) * GX_STRIDE + row] = v.w;
    }
    // W tile -> natural smem copy; 32 independent LDG.128/thread
    float* Wsf = (float*)Ws;
#pragma unroll
    for (int i = 0; i < 32; i++) {
        int idx = i * 128 + tx;        // 0..4095 float4s of the 128x128 tile
        int k  = idx >> 5;
        int cq = idx & 31;
        float4 v = *(const float4*)(W + (size_t)k * G_ + n0 + cq * 4);
        *(float4*)(Wsf + k * 128 + cq * 4) = v;
    }
    __syncthreads();

    int q  = tx & 7;           // owns col quads {4q, 32+4q, 64+4q, 96+4q}
    int rg = tx >> 3;          // 0..15 -> rows rg*4 .. rg*4+3
    int r0 = rg * 4;

    // acc[c][r]: c = 2*i+m -> cols 32*i + 4*q + 2*m + {0,1}; init with bias pair
    ull binit[8];
#pragma unroll
    for (int i = 0; i < 4; i++) {
#pragma unroll
        for (int m = 0; m < 2; m++) {
            int c = 32 * i + 4 * q + 2 * m;
            binit[2 * i + m] = pack2(bias[n0 + c], bias[n0 + c + 1]);
        }
    }
    ull acc[8][4];
#pragma unroll
    for (int c = 0; c < 8; c++)
#pragma unroll
        for (int r = 0; r < 4; r++) acc[c][r] = binit[c];

#pragma unroll 4
    for (int k = 0; k < 128; k++) {
        const float* xr = XsT + k * GX_STRIDE + r0;
        float2 xa = *(const float2*)(xr);
        float2 xb2v = *(const float2*)(xr + 2);
        ull x0 = pack_dup(xa.x);
        ull x1 = pack_dup(xa.y);
        ull x2 = pack_dup(xb2v.x);
        ull x3 = pack_dup(xb2v.y);
        const ull* wr = Ws + k * 64 + q * 2;
        ulonglong2 w0 = *(const ulonglong2*)(wr);        // cols 4q..4q+3
        ulonglong2 w1 = *(const ulonglong2*)(wr + 16);   // cols 32+4q..
        ulonglong2 w2 = *(const ulonglong2*)(wr + 32);   // cols 64+4q..
        ulonglong2 w3 = *(const ulonglong2*)(wr + 48);   // cols 96+4q..
        ffma2(acc[0][0], x0, w0.x); ffma2(acc[0][1], x1, w0.x); ffma2(acc[0][2], x2, w0.x); ffma2(acc[0][3], x3, w0.x);
        ffma2(acc[1][0], x0, w0.y); ffma2(acc[1][1], x1, w0.y); ffma2(acc[1][2], x2, w0.y); ffma2(acc[1][3], x3, w0.y);
        ffma2(acc[2][0], x0, w1.x); ffma2(acc[2][1], x1, w1.x); ffma2(acc[2][2], x2, w1.x); ffma2(acc[2][3], x3, w1.x);
        ffma2(acc[3][0], x0, w1.y); ffma2(acc[3][1], x1, w1.y); ffma2(acc[3][2], x2, w1.y); ffma2(acc[3][3], x3, w1.y);
        ffma2(acc[4][0], x0, w2.x); ffma2(acc[4][1], x1, w2.x); ffma2(acc[4][2], x2, w2.x); ffma2(acc[4][3], x3, w2.x);
        ffma2(acc[5][0], x0, w2.y); ffma2(acc[5][1], x1, w2.y); ffma2(acc[5][2], x2, w2.y); ffma2(acc[5][3], x3, w2.y);
        ffma2(acc[6][0], x0, w3.x); ffma2(acc[6][1], x1, w3.x); ffma2(acc[6][2], x2, w3.x); ffma2(acc[6][3], x3, w3.x);
        ffma2(acc[7][0], x0, w3.y); ffma2(acc[7][1], x1, w3.y); ffma2(acc[7][2], x2, w3.y); ffma2(acc[7][3], x3, w3.y);
    }

    // epilogue: float4 stores (bias already folded into acc init)
#pragma unroll
    for (int r = 0; r < 4; r++) {
        int t = t0 + r0 + r;
        if (t >= T_) continue;
        float* op = g_xm + ((size_t)b * T_ + t) * G_ + n0 + 4 * q;
#pragma unroll
        for (int i = 0; i < 4; i++) {
            float2 f0 = unpack2(acc[2 * i][r]);
            float2 f1 = unpack2(acc[2 * i + 1][r]);
            *(float4*)(op + 32 * i) = make_float4(f0.x, f0.y, f1.x, f1.y);
        }
    }
}

// ---------- Kernel 2: recurrence, split-k, balanced pass pairing ----------
// 128 blocks x 256 threads. Each block runs sorted group b, then group 255-b
// (first+last pairing => every block ~201 total steps, single wave).
// Warps 0-3 (group A, u=tid): kk 0..31; warps 4-7 (group B): kk 32..63.
// B writes partials to psum; A joins, computes gates, publishes h. 2 bars/step.
__global__ __launch_bounds__(256, 1) void recur_kernel(
    const int* __restrict__ slen, const float* __restrict__ R,
    const float* __restrict__ bias, float* __restrict__ out)
{
    extern __shared__ char smraw[];
    ull*    Rzr2 = (ull*)smraw;                                  // [64kk][128u][2] ull  131072
    float2* Rh2  = (float2*)(smraw + 131072);                    // [64kk][128u]          65536
    ull*    hd   = (ull*)(smraw + 131072 + 65536);               // [128k][4] dup pairs    4096
    ull*    hp   = (ull*)(smraw + 131072 + 65536 + 4096);        // [128k][2] row pairs    2048
    ull*    psum = (ull*)(smraw + 131072 + 65536 + 4096 + 2048); // [128u][6]              6144
    __shared__ int rows_s[4], len_s[4];

    int tid  = threadIdx.x;
    int u    = tid & 127;
    bool isA = tid < 128;

    // ---- R fill: 48 independent LDG.128/thread, scatter to packed layout ----
    {
        const float4* R4 = (const float4*)R;   // 12288 float4s
#pragma unroll 8
        for (int i = 0; i < 48; i++) {
            int f = i * 256 + tid;
            float4 v = R4[f];
            int k = f / 96;               // row of R
            int c = (f - k * 96) * 4;     // col 0..380, never crosses gate boundary
            int kk = k >> 1, kp = k & 1;
            if (c < 128) {
                float* dst = (float*)&Rzr2[(kk * 128 + c) * 2 + kp];             // rz lane
                dst[0] = v.x; dst[4] = v.y; dst[8] = v.z; dst[12] = v.w;
            } else if (c < 256) {
                float* dst = (float*)&Rzr2[(kk * 128 + (c - 128)) * 2 + kp] + 1; // rr lane
                dst[0] = v.x; dst[4] = v.y; dst[8] = v.z; dst[12] = v.w;
            } else {
                float* dst = (float*)&Rh2[kk * 128 + (c - 256)] + kp;
                dst[0] = v.x; dst[2] = v.y; dst[4] = v.z; dst[6] = v.w;
            }
        }
    }

    ull brzr = pack2(bias[G_ + u], bias[G_ + u + 128]);
    ull brh  = pack_dup(bias[G_ + u + 256]);

    int kk0 = isA ? 0 : 32;

    for (int pass = 0; pass < 2; pass++) {
        int gidx = (pass == 0) ? (int)blockIdx.x : (255 - (int)blockIdx.x);

        if (tid < 4) {
            int idx = B_ - 1 - (gidx * 4 + tid);   // descending lengths
            int row = g_perm[idx];
            rows_s[tid] = row;
            len_s[tid]  = slen[row];
        }
        // zero h buffers
        for (int i = tid; i < 128 * 4; i += 256) hd[i] = 0ULL;
        for (int i = tid; i < 128 * 2; i += 256) hp[i] = 0ULL;
        __syncthreads();

        int len0 = len_s[0], len1 = len_s[1], len2 = len_s[2], len3 = len_s[3];
        int maxlen = max(max(len0, len1), max(len2, len3));

        const float *xb0 = 0, *xb1 = 0, *xb2 = 0, *xb3 = 0;
        float *ob0 = 0, *ob1 = 0, *ob2 = 0, *ob3 = 0;
        if (isA) {
            xb0 = g_xm + (size_t)rows_s[0] * T_ * G_ + u;
            xb1 = g_xm + (size_t)rows_s[1] * T_ * G_ + u;
            xb2 = g_xm + (size_t)rows_s[2] * T_ * G_ + u;
            xb3 = g_xm + (size_t)rows_s[3] * T_ * G_ + u;
            ob0 = out + (size_t)rows_s[0] * T_ * U_ + u;
            ob1 = out + (size_t)rows_s[1] * T_ * U_ + u;
            ob2 = out + (size_t)rows_s[2] * T_ * U_ + u;
            ob3 = out + (size_t)rows_s[3] * T_ * U_ + u;
        }

        float h0 = 0.f, h1 = 0.f, h2 = 0.f, h3 = 0.f;
        float po0 = 0.f, po1 = 0.f, po2 = 0.f, po3 = 0.f;

        const ull*    Rp  = Rzr2 + u * 2;   // + kk*256
        const float2* Rhp = Rh2 + u;        // + kk*128

        for (int t = 0; t < maxlen; t++) {
            float xz0, xr0, xh0, xz1, xr1, xh1, xz2, xr2, xh2, xz3, xr3, xh3;
            if (isA) {
                size_t toff = (size_t)t * G_;
                xz0 = xb0[toff]; xr0 = xb0[toff + 128]; xh0 = xb0[toff + 256];
                xz1 = xb1[toff]; xr1 = xb1[toff + 128]; xh1 = xb1[toff + 256];
                xz2 = xb2[toff]; xr2 = xb2[toff + 128]; xh2 = xb2[toff + 256];
                xz3 = xb3[toff]; xr3 = xb3[toff + 128]; xh3 = xb3[toff + 256];
            }

            ull az0, az1, az2, az3, ah01, ah23;
            if (isA) { az0 = az1 = az2 = az3 = brzr; ah01 = ah23 = brh; az0 = brzr; }
            else     { az0 = az1 = az2 = az3 = 0ULL; ah01 = ah23 = 0ULL; }
            // note: bias added only once (A); B starts at zero.

#pragma unroll 4
            for (int kk = kk0; kk < kk0 + 32; kk++) {
                ulonglong2 rzr2 = *(const ulonglong2*)(Rp + kk * 256);
                float2 rh2v = Rhp[kk * 128];
                const ull* hck = hd + kk * 8;
                ulonglong2 hA0 = *(const ulonglong2*)(hck);       // k=2kk rows 0,1 dup
                ulonglong2 hB0 = *(const ulonglong2*)(hck + 2);   // k=2kk rows 2,3 dup
                ulonglong2 hA1 = *(const ulonglong2*)(hck + 4);   // k=2kk+1
                ulonglong2 hB1 = *(const ulonglong2*)(hck + 6);
                const ull* hpk = hp + kk * 4;
                ulonglong2 hp0 = *(const ulonglong2*)(hpk);       // k=2kk: (h0,h1),(h2,h3)
                ulonglong2 hp1 = *(const ulonglong2*)(hpk + 2);   // k=2kk+1
                ull rh0 = pack_dup(rh2v.x);
                ull rh1 = pack_dup(rh2v.y);
                ffma2(az0, hA0.x, rzr2.x); ffma2(az1, hA0.y, rzr2.x);
                ffma2(az2, hB0.x, rzr2.x); ffma2(az3, hB0.y, rzr2.x);
                ffma2(ah01, hp0.x, rh0);   ffma2(ah23, hp0.y, rh0);
                ffma2(az0, hA1.x, rzr2.y); ffma2(az1, hA1.y, rzr2.y);
                ffma2(az2, hB1.x, rzr2.y); ffma2(az3, hB1.y, rzr2.y);
                ffma2(ah01, hp1.x, rh1);   ffma2(ah23, hp1.y, rh1);
            }

            if (!isA) {
                ull* ps = psum + u * 6;
                ulonglong2 p0; p0.x = az0;  p0.y = az1;
                ulonglong2 p1; p1.x = az2;  p1.y = az3;
                ulonglong2 p2; p2.x = ah01; p2.y = ah23;
                *(ulonglong2*)(ps)     = p0;
                *(ulonglong2*)(ps + 2) = p1;
                *(ulonglong2*)(ps + 4) = p2;
            }
            __syncthreads();   // bar1: partials ready, all h reads done

            if (isA) {
                const ull* ps = psum + u * 6;
                ulonglong2 p0 = *(const ulonglong2*)(ps);
                ulonglong2 p1 = *(const ulonglong2*)(ps + 2);
                ulonglong2 p2 = *(const ulonglong2*)(ps + 4);
                az0  = addf2(az0, p0.x);  az1  = addf2(az1, p0.y);
                az2  = addf2(az2, p1.x);  az3  = addf2(az3, p1.y);
                ah01 = addf2(ah01, p2.x); ah23 = addf2(ah23, p2.y);

                float2 ap01 = unpack2(ah01);
                float2 ap23 = unpack2(ah23);
                {
                    float2 a = unpack2(az0);
                    float z = sigm(xz0 + a.x), r = sigm(xr0 + a.y);
                    float hh = tanh_fast(xh0 + r * ap01.x);
                    float v = z * h0 + (1.0f - z) * hh;
                    bool m = t < len0;
                    h0 = m ? v : h0; po0 = m ? v : po0;
                    ob0[(size_t)t * U_] = po0;
                }
                {
                    float2 a = unpack2(az1);
                    float z = sigm(xz1 + a.x), r = sigm(xr1 + a.y);
                    float hh = tanh_fast(xh1 + r * ap01.y);
                    float v = z * h1 + (1.0f - z) * hh;
                    bool m = t < len1;
                    h1 = m ? v : h1; po1 = m ? v : po1;
                    ob1[(size_t)t * U_] = po1;
                }
                {
                    float2 a = unpack2(az2);
                    float z = sigm(xz2 + a.x), r = sigm(xr2 + a.y);
                    float hh = tanh_fast(xh2 + r * ap23.x);
                    float v = z * h2 + (1.0f - z) * hh;
                    bool m = t < len2;
                    h2 = m ? v : h2; po2 = m ? v : po2;
                    ob2[(size_t)t * U_] = po2;
                }
                {
                    float2 a = unpack2(az3);
                    float z = sigm(xz3 + a.x), r = sigm(xr3 + a.y);
                    float hh = tanh_fast(xh3 + r * ap23.y);
                    float v = z * h3 + (1.0f - z) * hh;
                    bool m = t < len3;
                    h3 = m ? v : h3; po3 = m ? v : po3;
                    ob3[(size_t)t * U_] = po3;
                }
                // publish next-step h: dup pairs + row pairs (single buffer, safe:
                // B is parked at bar2 and all reads completed before bar1)
                uint4 w0, w1, wp;
                w0.x = __float_as_uint(h0); w0.y = w0.x;
                w0.z = __float_as_uint(h1); w0.w = w0.z;
                w1.x = __float_as_uint(h2); w1.y = w1.x;
                w1.z = __float_as_uint(h3); w1.w = w1.z;
                wp.x = __float_as_uint(h0); wp.y = __float_as_uint(h1);
                wp.z = __float_as_uint(h2); wp.w = __float_as_uint(h3);
                *(uint4*)(hd + u * 4)     = w0;
                *(uint4*)(hd + u * 4 + 2) = w1;
                *(uint4*)(hp + u * 2)     = wp;
            }
            __syncthreads();   // bar2: new h published
        }

        // tail: frozen outputs (A only; pure stores)
        if (isA) {
            for (int t = maxlen; t < T_; t++) {
                ob0[(size_t)t * U_] = po0;
                ob1[(size_t)t * U_] = po1;
                ob2[(size_t)t * U_] = po2;
                ob3[(size_t)t * U_] = po3;
            }
        }
        __syncthreads();   // protect rows_s/len_s + h buffers before next pass
    }
}

extern "C" void kernel_launch(void* const* d_in, const int* in_sizes, int n_in,
                              void* d_out, int out_size)
{
    const float* X    = (const float*)d_in[0];   // [B][T][D]
    const int*   slen = (const int*)d_in[1];     // [B][1]
    const float* W    = (const float*)d_in[2];   // [D][3U]
    const float* R    = (const float*)d_in[3];   // [U][3U]
    const float* bias = (const float*)d_in[4];   // [2][3U]
    float* out = (float*)d_out;                  // [B][T][U]

    (void)in_sizes; (void)n_in; (void)out_size;

    const int gemm_smem  = 128 * GX_STRIDE * 4 + 128 * 64 * 8;          // 99328 B
    const int recur_smem = 131072 + 65536 + 4096 + 2048 + 6144;         // 208896 B

    cudaFuncSetAttribute(gemm_in_kernel, cudaFuncAttributeMaxDynamicSharedMemorySize, gemm_smem);
    cudaFuncSetAttribute(recur_kernel,  cudaFuncAttributeMaxDynamicSharedMemorySize, recur_smem);

    sort_rows_kernel<<<1, B_>>>(slen);

    dim3 ggrid(3, 4, B_);   // 3 col-tiles of 128, 4 t-tiles of 64, B
    gemm_in_kernel<<<ggrid, 128, gemm_smem>>>(X, slen, W, bias);

    recur_kernel<<<128, 256, recur_smem>>>(slen, R, bias, out);
}

// round 6
// speedup vs baseline: 1.7471x; 1.1321x over previous
#include <cuda_runtime.h>
#include <cuda_bf16.h>
#include <cstdint>

#define B_ 1024
#define T_ 200
#define D_ 128
#define U_ 128
#define G_ 384   // 3*U

typedef unsigned long long ull;

// Scratch (no cudaMalloc allowed): xm = X@W + b_in, [B][T][3U]; split-W; perm.
__device__ float g_xm[(size_t)B_ * T_ * G_];
__device__ int   g_perm[B_];
__device__ __nv_bfloat16 g_whi[G_ * D_];   // [g][k] transposed hi(W)
__device__ __nv_bfloat16 g_wlo[G_ * D_];   // [g][k] transposed lo(W)

// ---------- f32x2 helpers ----------
__device__ __forceinline__ ull pack_dup(float x) {
    ull r; asm("mov.b64 %0, {%1, %1};" : "=l"(r) : "f"(x)); return r;
}
__device__ __forceinline__ ull pack2(float x, float y) {
    ull r; asm("mov.b64 %0, {%1, %2};" : "=l"(r) : "f"(x), "f"(y)); return r;
}
__device__ __forceinline__ void ffma2(ull& d, ull a, ull b) {
    asm("fma.rn.f32x2 %0, %1, %2, %0;" : "+l"(d) : "l"(a), "l"(b));
}
__device__ __forceinline__ ull addf2(ull a, ull b) {
    ull r; asm("add.rn.f32x2 %0, %1, %2;" : "=l"(r) : "l"(a), "l"(b)); return r;
}
__device__ __forceinline__ float2 unpack2(ull v) {
    float2 f; asm("mov.b64 {%0, %1}, %2;" : "=f"(f.x), "=f"(f.y) : "l"(v)); return f;
}
__device__ __forceinline__ float sigm(float x) {
    return __fdividef(1.0f, 1.0f + __expf(-x));
}
__device__ __forceinline__ float tanh_fast(float x) {
    return 1.0f - __fdividef(2.0f, __expf(2.0f * x) + 1.0f);
}

// ---------- tensor helpers ----------
__device__ __forceinline__ void ldsm4(uint32_t& r0, uint32_t& r1, uint32_t& r2, uint32_t& r3, uint32_t addr) {
    asm volatile("ldmatrix.sync.aligned.m8n8.x4.shared.b16 {%0,%1,%2,%3}, [%4];"
                 : "=r"(r0), "=r"(r1), "=r"(r2), "=r"(r3) : "r"(addr));
}
__device__ __forceinline__ void mma16816(float* d, uint32_t a0, uint32_t a1, uint32_t a2, uint32_t a3,
                                         uint32_t b0, uint32_t b1) {
    asm volatile("mma.sync.aligned.m16n8k16.row.col.f32.bf16.bf16.f32 "
                 "{%0,%1,%2,%3},{%4,%5,%6,%7},{%8,%9},{%0,%1,%2,%3};"
                 : "+f"(d[0]), "+f"(d[1]), "+f"(d[2]), "+f"(d[3])
                 : "r"(a0), "r"(a1), "r"(a2), "r"(a3), "r"(b0), "r"(b1));
}
__device__ __forceinline__ uint32_t pack_bf2(__nv_bfloat16 a, __nv_bfloat16 b) {
    uint16_t ua = *(uint16_t*)&a, ub = *(uint16_t*)&b;
    return (uint32_t)ua | ((uint32_t)ub << 16);
}

// ---------- Kernel 0: bitonic sort of batch rows by length (ascending) ----------
__global__ void sort_rows_kernel(const int* __restrict__ slen) {
    __shared__ int key[B_];
    int tid = threadIdx.x;
    key[tid] = slen[tid] * 1024 + tid;
    __syncthreads();
    for (int size = 2; size <= B_; size <<= 1) {
        for (int stride = size >> 1; stride > 0; stride >>= 1) {
            int j = tid ^ stride;
            if (j > tid) {
                int a = key[tid], b = key[j];
                bool up = (tid & size) == 0;
                if ((a > b) == up) { key[tid] = b; key[j] = a; }
            }
            __syncthreads();
        }
    }
    g_perm[tid] = key[tid] & (B_ - 1);
}

// ---------- Kernel 0b: split W into transposed bf16 hi/lo ----------
__global__ void wsplit_kernel(const float* __restrict__ W) {
    int idx = blockIdx.x * 256 + threadIdx.x;   // 49152 = 128*384
    int k = idx / G_, g = idx - k * G_;
    float w = W[(size_t)k * G_ + g];
    __nv_bfloat16 hi = __float2bfloat16(w);
    __nv_bfloat16 lo = __float2bfloat16(w - __bfloat162float(hi));
    g_whi[g * D_ + k] = hi;
    g_wlo[g * D_ + k] = lo;
}

// ---------- Kernel 1: input GEMM via bf16-split-3 tensor cores ----------
// Block tile M=64 t-rows x N=128 gate-cols, 256 threads (8 warps: 4 in M x 2 in N).
// K=384 effective: (Xhi,Whi) + (Xhi,Wlo) + (Xlo,Whi), all tiles smem-resident (98KB).
__global__ __launch_bounds__(256, 2) void gemm_in_kernel(
    const float* __restrict__ X, const int* __restrict__ slen,
    const float* __restrict__ bias)
{
    int b  = blockIdx.z;
    int t0 = blockIdx.y * 64;
    int n0 = blockIdx.x * 128;
    if (t0 >= slen[b]) return;

    extern __shared__ char smem[];
    __nv_bfloat16* Xhi = (__nv_bfloat16*)smem;   // [64][128]
    __nv_bfloat16* Xlo = Xhi + 64 * 128;         // [64][128]
    __nv_bfloat16* Whi = Xlo + 64 * 128;         // [128][128]  (rows = gate col, cols = k)
    __nv_bfloat16* Wlo = Whi + 128 * 128;        // [128][128]
    int tid = threadIdx.x;

    // X fill: split to hi/lo, swizzled (16B chunk c -> c ^ (row&7))
    const float4* Xg = (const float4*)(X + (size_t)b * T_ * D_);
#pragma unroll
    for (int i = 0; i < 8; i++) {
        int idx = i * 256 + tid;           // 2048 float4s
        int row = idx >> 5, dq = idx & 31; // dq = float4 index along D
        int t = t0 + row;
        float4 v = make_float4(0.f, 0.f, 0.f, 0.f);
        if (t < T_) v = Xg[t * 32 + dq];
        __nv_bfloat16 hx = __float2bfloat16(v.x), hy = __float2bfloat16(v.y);
        __nv_bfloat16 hz = __float2bfloat16(v.z), hw = __float2bfloat16(v.w);
        __nv_bfloat16 lx = __float2bfloat16(v.x - __bfloat162float(hx));
        __nv_bfloat16 ly = __float2bfloat16(v.y - __bfloat162float(hy));
        __nv_bfloat16 lz = __float2bfloat16(v.z - __bfloat162float(hz));
        __nv_bfloat16 lw = __float2bfloat16(v.w - __bfloat162float(hw));
        int off = row * 128 + (((dq >> 1) ^ (row & 7)) << 3) + (dq & 1) * 4;  // halves
        uint2 hv; hv.x = pack_bf2(hx, hy); hv.y = pack_bf2(hz, hw);
        uint2 lv; lv.x = pack_bf2(lx, ly); lv.y = pack_bf2(lz, lw);
        *(uint2*)(Xhi + off) = hv;
        *(uint2*)(Xlo + off) = lv;
    }
    // W fill: copy bf16 rows (gate cols n0..n0+127), swizzled
    const uint4* WhiG = (const uint4*)g_whi;   // [g][16 x uint4]
    const uint4* WloG = (const uint4*)g_wlo;
#pragma unroll
    for (int i = 0; i < 8; i++) {
        int idx = i * 256 + tid;          // 2048 uint4s
        int n = idx >> 4, c8 = idx & 15;
        int src = (n0 + n) * 16 + c8;
        int dst = n * 16 + (c8 ^ (n & 7));
        ((uint4*)Whi)[dst] = WhiG[src];
        ((uint4*)Wlo)[dst] = WloG[src];
    }
    __syncthreads();

    int lane = tid & 31, wid = tid >> 5;
    int m_off = (wid & 3) * 16;
    int n_off = (wid >> 2) * 64;

    uint32_t XhiB = (uint32_t)__cvta_generic_to_shared(Xhi);
    uint32_t XloB = (uint32_t)__cvta_generic_to_shared(Xlo);
    uint32_t WhiB = (uint32_t)__cvta_generic_to_shared(Whi);
    uint32_t WloB = (uint32_t)__cvta_generic_to_shared(Wlo);

    int ar = m_off + (lane & 15);
    uint32_t arow = ar * 256, axor = (ar & 7), ahi = lane >> 4;
    int brn = n_off + ((lane >> 4) << 3) + (lane & 7);
    uint32_t brow0 = brn * 256, bxor = (brn & 7), bhi = (lane >> 3) & 1;

    float d[8][4];
#pragma unroll
    for (int f = 0; f < 8; f++)
#pragma unroll
        for (int r = 0; r < 4; r++) d[f][r] = 0.f;

#pragma unroll
    for (int ch = 0; ch < 3; ch++) {
        uint32_t Ab = (ch < 2) ? XhiB : XloB;
        uint32_t Bb = (ch == 1) ? WloB : WhiB;
#pragma unroll
        for (int ks = 0; ks < 8; ks++) {
            uint32_t c = ks * 2;
            uint32_t a0, a1, a2, a3;
            ldsm4(a0, a1, a2, a3, Ab + arow + (((c + ahi) ^ axor) << 4));
#pragma unroll
            for (int nb = 0; nb < 4; nb++) {
                uint32_t b0, b1, b2, b3;
                ldsm4(b0, b1, b2, b3, Bb + brow0 + nb * 16 * 256 + (((c + bhi) ^ bxor) << 4));
                mma16816(d[2 * nb],     a0, a1, a2, a3, b0, b1);
                mma16816(d[2 * nb + 1], a0, a1, a2, a3, b2, b3);
            }
        }
    }

    // epilogue: bias + fp32 stores
    int rloc = m_off + (lane >> 2);
    int trow0 = t0 + rloc, trow1 = trow0 + 8;
    float* o0 = g_xm + ((size_t)b * T_ + trow0) * G_ + n0;
    float* o1 = g_xm + ((size_t)b * T_ + trow1) * G_ + n0;
#pragma unroll
    for (int f = 0; f < 8; f++) {
        int col = n_off + (f >> 1) * 16 + (f & 1) * 8 + (lane & 3) * 2;
        float2 bv = *(const float2*)(bias + n0 + col);
        if (trow0 < T_) *(float2*)(o0 + col) = make_float2(d[f][0] + bv.x, d[f][1] + bv.y);
        if (trow1 < T_) *(float2*)(o1 + col) = make_float2(d[f][2] + bv.x, d[f][3] + bv.y);
    }
}

// ---------- Kernel 2: recurrence, split-k + parallel gates, balanced pairing ----------
// 128 blocks x 256 threads, 2 passes (group b then 255-b). Warps A (tid<128): kk 0..31,
// gates rows 0,1; warps B: kk 32..63, gates rows 2,3. Symmetric psum exchange.
__global__ __launch_bounds__(256, 1) void recur_kernel(
    const int* __restrict__ slen, const float* __restrict__ R,
    const float* __restrict__ bias, float* __restrict__ out)
{
    extern __shared__ char smraw[];
    ull*    Rzr2 = (ull*)smraw;                                  // [64kk][128u][2]  131072
    float2* Rh2  = (float2*)(smraw + 131072);                    // [64kk][128u]      65536
    ull*    hd   = (ull*)(smraw + 131072 + 65536);               // [128k][4] dup      4096
    ull*    hp   = (ull*)(smraw + 131072 + 65536 + 4096);        // [128k][2] pairs    2048
    ull*    psum = (ull*)(smraw + 131072 + 65536 + 4096 + 2048); // [128u][6]          6144
    __shared__ int rows_s[4], len_s[4];

    int tid  = threadIdx.x;
    int u    = tid & 127;
    bool isA = tid < 128;

    // R fill: packed layout
    {
        const float4* R4 = (const float4*)R;
#pragma unroll 8
        for (int i = 0; i < 48; i++) {
            int f = i * 256 + tid;
            float4 v = R4[f];
            int k = f / 96;
            int c = (f - k * 96) * 4;
            int kk = k >> 1, kp = k & 1;
            if (c < 128) {
                float* dst = (float*)&Rzr2[(kk * 128 + c) * 2 + kp];
                dst[0] = v.x; dst[4] = v.y; dst[8] = v.z; dst[12] = v.w;
            } else if (c < 256) {
                float* dst = (float*)&Rzr2[(kk * 128 + (c - 128)) * 2 + kp] + 1;
                dst[0] = v.x; dst[4] = v.y; dst[8] = v.z; dst[12] = v.w;
            } else {
                float* dst = (float*)&Rh2[kk * 128 + (c - 256)] + kp;
                dst[0] = v.x; dst[2] = v.y; dst[4] = v.z; dst[6] = v.w;
            }
        }
    }

    ull brzr = pack2(bias[G_ + u], bias[G_ + u + 128]);
    ull brh  = pack_dup(bias[G_ + u + 256]);

    int kk0 = isA ? 0 : 32;
    int rP = isA ? 0 : 2;   // this side's two rows

    for (int pass = 0; pass < 2; pass++) {
        int gidx = (pass == 0) ? (int)blockIdx.x : (255 - (int)blockIdx.x);

        if (tid < 4) {
            int idx = B_ - 1 - (gidx * 4 + tid);
            int row = g_perm[idx];
            rows_s[tid] = row;
            len_s[tid]  = slen[row];
        }
        for (int i = tid; i < 128 * 4; i += 256) hd[i] = 0ULL;
        for (int i = tid; i < 128 * 2; i += 256) hp[i] = 0ULL;
        __syncthreads();

        int maxlen = max(max(len_s[0], len_s[1]), max(len_s[2], len_s[3]));
        int lenP = len_s[rP], lenQ = len_s[rP + 1];

        const float* xbP = g_xm + (size_t)rows_s[rP] * T_ * G_ + u;
        const float* xbQ = g_xm + (size_t)rows_s[rP + 1] * T_ * G_ + u;
        float* obP = out + (size_t)rows_s[rP] * T_ * U_ + u;
        float* obQ = out + (size_t)rows_s[rP + 1] * T_ * U_ + u;

        float hP = 0.f, hQ = 0.f, poP = 0.f, poQ = 0.f;

        const ull*    Rp  = Rzr2 + u * 2;
        const float2* Rhp = Rh2 + u;

        for (int t = 0; t < maxlen; t++) {
            size_t toff = (size_t)t * G_;
            float xzP = xbP[toff], xrP = xbP[toff + 128], xhP = xbP[toff + 256];
            float xzQ = xbQ[toff], xrQ = xbQ[toff + 128], xhQ = xbQ[toff + 256];

            ull az0, az1, az2, az3, ah01, ah23;
            if (isA) { az0 = az1 = az2 = az3 = brzr; ah01 = ah23 = brh; }
            else     { az0 = az1 = az2 = az3 = 0ULL; ah01 = ah23 = 0ULL; }

#pragma unroll 4
            for (int kk = kk0; kk < kk0 + 32; kk++) {
                ulonglong2 rzr2 = *(const ulonglong2*)(Rp + kk * 256);
                float2 rh2v = Rhp[kk * 128];
                const ull* hck = hd + kk * 8;
                ulonglong2 hA0 = *(const ulonglong2*)(hck);
                ulonglong2 hB0 = *(const ulonglong2*)(hck + 2);
                ulonglong2 hA1 = *(const ulonglong2*)(hck + 4);
                ulonglong2 hB1 = *(const ulonglong2*)(hck + 6);
                const ull* hpk = hp + kk * 4;
                ulonglong2 hp0 = *(const ulonglong2*)(hpk);
                ulonglong2 hp1 = *(const ulonglong2*)(hpk + 2);
                ull rh0 = pack_dup(rh2v.x);
                ull rh1 = pack_dup(rh2v.y);
                ffma2(az0, hA0.x, rzr2.x); ffma2(az1, hA0.y, rzr2.x);
                ffma2(az2, hB0.x, rzr2.x); ffma2(az3, hB0.y, rzr2.x);
                ffma2(ah01, hp0.x, rh0);   ffma2(ah23, hp0.y, rh0);
                ffma2(az0, hA1.x, rzr2.y); ffma2(az1, hA1.y, rzr2.y);
                ffma2(az2, hB1.x, rzr2.y); ffma2(az3, hB1.y, rzr2.y);
                ffma2(ah01, hp1.x, rh1);   ffma2(ah23, hp1.y, rh1);
            }

            // symmetric exchange: each side posts the other side's rows
            {
                ull* ps = psum + u * 6;
                if (isA) { ps[3] = az2; ps[4] = az3; ps[5] = ah23; }
                else     { ps[0] = az0; ps[1] = az1; ps[2] = ah01; }
            }
            __syncthreads();   // bar1: partials ready, all h reads done

            {
                const ull* ps = psum + u * 6;
                ull e0, e1, eh;
                if (isA) { e0 = addf2(az0, ps[0]); e1 = addf2(az1, ps[1]); eh = addf2(ah01, ps[2]); }
                else     { e0 = addf2(az2, ps[3]); e1 = addf2(az3, ps[4]); eh = addf2(ah23, ps[5]); }

                float2 aP = unpack2(e0), aQ = unpack2(e1), ahv = unpack2(eh);
                {
                    float z = sigm(xzP + aP.x), r = sigm(xrP + aP.y);
                    float hh = tanh_fast(xhP + r * ahv.x);
                    float v = z * hP + (1.0f - z) * hh;
                    bool m = t < lenP;
                    hP = m ? v : hP; poP = m ? v : poP;
                    obP[(size_t)t * U_] = poP;
                }
                {
                    float z = sigm(xzQ + aQ.x), r = sigm(xrQ + aQ.y);
                    float hh = tanh_fast(xhQ + r * ahv.y);
                    float v = z * hQ + (1.0f - z) * hh;
                    bool m = t < lenQ;
                    hQ = m ? v : hQ; poQ = m ? v : poQ;
                    obQ[(size_t)t * U_] = poQ;
                }
                // publish this side's h (dup + pair)
                uint2 wd0, wd1;
                wd0.x = __float_as_uint(hP); wd0.y = wd0.x;
                wd1.x = __float_as_uint(hQ); wd1.y = wd1.x;
                int base = isA ? 0 : 2;
                *(uint2*)(hd + u * 4 + base)     = wd0;
                *(uint2*)(hd + u * 4 + base + 1) = wd1;
                hp[u * 2 + (isA ? 0 : 1)] = pack2(hP, hQ);
            }
            __syncthreads();   // bar2: new h published
        }

        // tail: frozen outputs
        for (int t = maxlen; t < T_; t++) {
            obP[(size_t)t * U_] = poP;
            obQ[(size_t)t * U_] = poQ;
        }
        __syncthreads();
    }
}

extern "C" void kernel_launch(void* const* d_in, const int* in_sizes, int n_in,
                              void* d_out, int out_size)
{
    const float* X    = (const float*)d_in[0];   // [B][T][D]
    const int*   slen = (const int*)d_in[1];     // [B][1]
    const float* W    = (const float*)d_in[2];   // [D][3U]
    const float* R    = (const float*)d_in[3];   // [U][3U]
    const float* bias = (const float*)d_in[4];   // [2][3U]
    float* out = (float*)d_out;                  // [B][T][U]

    (void)in_sizes; (void)n_in; (void)out_size;

    const int gemm_smem  = (64 * 128 * 2 + 128 * 128 * 2) * 2;   // 98304 B
    const int recur_smem = 131072 + 65536 + 4096 + 2048 + 6144;  // 208896 B

    cudaFuncSetAttribute(gemm_in_kernel, cudaFuncAttributeMaxDynamicSharedMemorySize, gemm_smem);
    cudaFuncSetAttribute(recur_kernel,  cudaFuncAttributeMaxDynamicSharedMemorySize, recur_smem);

    sort_rows_kernel<<<1, B_>>>(slen);
    wsplit_kernel<<<192, 256>>>(W);

    dim3 ggrid(3, 4, B_);   // 3 col-tiles of 128, 4 t-tiles of 64, B
    gemm_in_kernel<<<ggrid, 256, gemm_smem>>>(X, slen, bias);

    recur_kernel<<<128, 256, recur_smem>>>(slen, R, bias, out);
}